// round 1
// baseline (speedup 1.0000x reference)
#include <cuda_runtime.h>
#include <math.h>

// ---------------- problem constants ----------------
#define BATCH   8
#define NC      3
#define HH      24
#define WW      150
#define PP      2
#define WSEG    75           // WW/PP
#define NTOK    1800         // HH*WSEG
#define PD      6            // PP*NC
#define DIM     512
#define LAYERS  4
#define NHEAD   8
#define DHEAD   64
#define MLPD    2048
#define NMASK   900
#define MTOK    (BATCH*NTOK) // 14400 total tokens
#define SCALE   0.125f       // 1/sqrt(64)

// ---------------- scratch (device globals; allocation-free) ----------------
__device__ float  g_x  [(size_t)MTOK * DIM];
__device__ float  g_h  [(size_t)MTOK * DIM];
__device__ float  g_qkv[(size_t)MTOK * 3 * DIM];
__device__ float  g_ao [(size_t)MTOK * DIM];
__device__ float  g_mlp[(size_t)MTOK * MLPD];
__device__ int    g_mask[MTOK];
__device__ double g_sum;

// ---------------- helpers ----------------
__device__ __forceinline__ float gelu_tanh(float x) {
    // jax.nn.gelu(approximate=True)
    const float c = 0.7978845608028654f;
    float x3 = x * x * x;
    float t  = tanhf(c * (x + 0.044715f * x3));
    return 0.5f * x * (1.0f + t);
}

// ---------------- setup kernels ----------------
__global__ void zero_k() {
    int i = blockIdx.x * 256 + threadIdx.x;
    if (i < MTOK) g_mask[i] = 0;
    if (i == 0)   g_sum = 0.0;
}

__global__ void scat_k(const int* __restrict__ midx) {
    int i = blockIdx.x * 256 + threadIdx.x;
    if (i < BATCH * NMASK) {
        int b = i / NMASK;
        g_mask[b * NTOK + midx[i]] = 1;
    }
}

// x[b,n,:] = masked ? mask_token+pos : patch@W+b+pos
__global__ __launch_bounds__(128) void build_x_k(
    const float* __restrict__ img, const float* __restrict__ pos_table,
    const float* __restrict__ val_table, const float* __restrict__ patch_W,
    const float* __restrict__ patch_b, const float* __restrict__ mask_token,
    const int* __restrict__ valid_length)
{
    int n = blockIdx.x, b = blockIdx.y, t = threadIdx.x;
    __shared__ float pv[PD];
    __shared__ int   sm_mask, sm_seg;
    int hh = n / WSEG, ws = n % WSEG;
    if (t < PD) {
        int p = t / NC, c = t % NC;
        pv[t] = img[(((size_t)b * NC + c) * HH + hh) * WW + ws * PP + p];
    } else if (t == 8) {
        sm_mask = g_mask[b * NTOK + n];
    } else if (t == 9) {
        int vl = valid_length[b];
        if (vl == 150) vl = 149;
        int nv = (vl + 1) >> 1;
        sm_seg = (ws < nv) ? 1 : 0;
    }
    __syncthreads();
    float p0 = pv[0], p1 = pv[1], p2 = pv[2], p3 = pv[3], p4 = pv[4], p5 = pv[5];
    int msk = sm_mask, seg = sm_seg;
    size_t rowo = ((size_t)(b * NTOK + n)) * DIM;
    for (int d = t; d < DIM; d += 128) {
        float pos = pos_table[(size_t)(n + 1) * DIM + d] + val_table[(size_t)seg * DIM + d];
        float v;
        if (msk) {
            v = mask_token[d] + pos;
        } else {
            v = patch_b[d]
              + p0 * patch_W[0 * DIM + d] + p1 * patch_W[1 * DIM + d]
              + p2 * patch_W[2 * DIM + d] + p3 * patch_W[3 * DIM + d]
              + p4 * patch_W[4 * DIM + d] + p5 * patch_W[5 * DIM + d];
            v += pos;
        }
        g_x[rowo + d] = v;
    }
}

// ---------------- layernorm ----------------
__global__ __launch_bounds__(256) void ln_k(
    const float* __restrict__ x, const float* __restrict__ gam,
    const float* __restrict__ bet, float* __restrict__ out)
{
    int r = blockIdx.x, t = threadIdx.x;
    const float* xr = x + (size_t)r * DIM;
    float v0 = xr[t], v1 = xr[t + 256];
    float sum = v0 + v1;
    float sq  = v0 * v0 + v1 * v1;
    __shared__ float sh[64];
    #pragma unroll
    for (int o = 16; o > 0; o >>= 1) {
        sum += __shfl_xor_sync(0xffffffffu, sum, o);
        sq  += __shfl_xor_sync(0xffffffffu, sq,  o);
    }
    int warp = t >> 5, lane = t & 31;
    if (lane == 0) { sh[warp] = sum; sh[warp + 32] = sq; }
    __syncthreads();
    if (t == 0) {
        float ts = 0.f, tq = 0.f;
        #pragma unroll
        for (int i = 0; i < 8; i++) { ts += sh[i]; tq += sh[32 + i]; }
        float mean = ts * (1.0f / DIM);
        float var  = tq * (1.0f / DIM) - mean * mean;
        sh[0] = mean;
        sh[1] = rsqrtf(var + 1e-5f);
    }
    __syncthreads();
    float mean = sh[0], rstd = sh[1];
    out[(size_t)r * DIM + t]       = (v0 - mean) * rstd * gam[t]       + bet[t];
    out[(size_t)r * DIM + t + 256] = (v1 - mean) * rstd * gam[t + 256] + bet[t + 256];
}

// ---------------- tiled SGEMM with fused epilogue ----------------
// C[M,N] = epi( A[M,K] @ W[K,N] + bias[N] )   EPI: 0=none, 1=gelu, 2=+R
#define BM 128
#define BN 128
#define BK 8
template <int EPI>
__global__ __launch_bounds__(256) void gemm_k(
    const float* __restrict__ A, const float* __restrict__ W,
    const float* __restrict__ bias, const float* __restrict__ R,
    float* __restrict__ C, int M, int N, int K)
{
    __shared__ __align__(16) float As[BK][BM];
    __shared__ __align__(16) float Bs[BK][BN];
    int tid = threadIdx.x;
    int m0  = blockIdx.y * BM;
    int n0  = blockIdx.x * BN;
    int tx  = tid & 15, ty = tid >> 4;

    float acc[8][8];
    #pragma unroll
    for (int i = 0; i < 8; i++)
        #pragma unroll
        for (int j = 0; j < 8; j++) acc[i][j] = 0.f;

    int arow = tid >> 1;
    int acol = (tid & 1) * 4;
    int wrow = tid >> 5;
    int wcol = (tid & 31) * 4;

    for (int k0 = 0; k0 < K; k0 += BK) {
        float4 av;
        if (m0 + arow < M) av = *(const float4*)&A[(size_t)(m0 + arow) * K + k0 + acol];
        else               av = make_float4(0.f, 0.f, 0.f, 0.f);
        As[acol + 0][arow] = av.x;
        As[acol + 1][arow] = av.y;
        As[acol + 2][arow] = av.z;
        As[acol + 3][arow] = av.w;
        float4 wv = *(const float4*)&W[(size_t)(k0 + wrow) * N + n0 + wcol];
        *(float4*)&Bs[wrow][wcol] = wv;
        __syncthreads();
        #pragma unroll
        for (int kk = 0; kk < BK; kk++) {
            float ra[8], rb[8];
            #pragma unroll
            for (int i = 0; i < 8; i++) ra[i] = As[kk][ty * 8 + i];
            #pragma unroll
            for (int j = 0; j < 8; j++) rb[j] = Bs[kk][tx * 8 + j];
            #pragma unroll
            for (int i = 0; i < 8; i++)
                #pragma unroll
                for (int j = 0; j < 8; j++)
                    acc[i][j] += ra[i] * rb[j];
        }
        __syncthreads();
    }

    #pragma unroll
    for (int i = 0; i < 8; i++) {
        int row = m0 + ty * 8 + i;
        if (row >= M) continue;
        #pragma unroll
        for (int j = 0; j < 8; j++) {
            int col = n0 + tx * 8 + j;
            float v = acc[i][j] + bias[col];
            if (EPI == 1) v = gelu_tanh(v);
            if (EPI == 2) v += R[(size_t)row * N + col];
            C[(size_t)row * N + col] = v;
        }
    }
}

// ---------------- flash attention (fp32, 1 query per thread) ----------------
__global__ __launch_bounds__(128) void attn_k(const float* __restrict__ qkv,
                                              float* __restrict__ out)
{
    int b = blockIdx.z, h = blockIdx.y;
    int q = blockIdx.x * 128 + threadIdx.x;
    int tid = threadIdx.x;
    bool qvalid = (q < NTOK);

    __shared__ __align__(16) float Ks[16][DHEAD];
    __shared__ __align__(16) float Vs[16][DHEAD];

    float qreg[DHEAD];
    {
        const float* qptr = qkv + ((size_t)(b * NTOK + (qvalid ? q : 0))) * (3 * DIM) + h * DHEAD;
        #pragma unroll
        for (int d = 0; d < DHEAD; d++) qreg[d] = qptr[d] * SCALE;
    }

    float m = -1e30f, l = 0.f;
    float o[DHEAD];
    #pragma unroll
    for (int d = 0; d < DHEAD; d++) o[d] = 0.f;

    for (int t0 = 0; t0 < NTOK; t0 += 16) {
        __syncthreads();
        // cooperative load of 16x64 K and V tiles (2 float4 per thread per tile)
        #pragma unroll
        for (int i = 0; i < 2; i++) {
            int f  = tid * 2 + i;       // 0..255 float4 slots
            int j  = f >> 4;            // key row in tile
            int dc = (f & 15) * 4;      // dim offset
            int kr = t0 + j;
            float4 kv, vv;
            if (kr < NTOK) {
                const float* base = qkv + ((size_t)(b * NTOK + kr)) * (3 * DIM) + h * DHEAD;
                kv = *(const float4*)(base + DIM + dc);
                vv = *(const float4*)(base + 2 * DIM + dc);
            } else {
                kv = make_float4(0.f, 0.f, 0.f, 0.f);
                vv = kv;
            }
            *(float4*)&Ks[j][dc] = kv;
            *(float4*)&Vs[j][dc] = vv;
        }
        __syncthreads();

        int nk = NTOK - t0; if (nk > 16) nk = 16;
        float s[16];
        #pragma unroll
        for (int j = 0; j < 16; j++) {
            const float4* K4 = (const float4*)Ks[j];
            float a0 = 0.f, a1 = 0.f, a2 = 0.f, a3 = 0.f;
            #pragma unroll
            for (int d4 = 0; d4 < 16; d4++) {
                float4 kv = K4[d4];
                a0 += qreg[4 * d4 + 0] * kv.x;
                a1 += qreg[4 * d4 + 1] * kv.y;
                a2 += qreg[4 * d4 + 2] * kv.z;
                a3 += qreg[4 * d4 + 3] * kv.w;
            }
            s[j] = (a0 + a1) + (a2 + a3);
        }
        float mt = -1e30f;
        for (int j = 0; j < nk; j++) mt = fmaxf(mt, s[j]);
        float mn = fmaxf(m, mt);
        float corr = __expf(m - mn);
        l *= corr;
        #pragma unroll
        for (int d = 0; d < DHEAD; d++) o[d] *= corr;
        for (int j = 0; j < nk; j++) {
            float p = __expf(s[j] - mn);
            l += p;
            const float4* V4 = (const float4*)Vs[j];
            #pragma unroll
            for (int d4 = 0; d4 < 16; d4++) {
                float4 vv = V4[d4];
                o[4 * d4 + 0] += p * vv.x;
                o[4 * d4 + 1] += p * vv.y;
                o[4 * d4 + 2] += p * vv.z;
                o[4 * d4 + 3] += p * vv.w;
            }
        }
        m = mn;
    }

    if (qvalid) {
        float inv = 1.0f / l;
        float* op = out + ((size_t)(b * NTOK + q)) * DIM + h * DHEAD;
        #pragma unroll
        for (int d = 0; d < DHEAD; d++) op[d] = o[d] * inv;
    }
}

// ---------------- masked-patch prediction + L1 loss ----------------
__global__ __launch_bounds__(192) void loss_k(
    const float* __restrict__ xenc, const int* __restrict__ midx,
    const float* __restrict__ Wt, const float* __restrict__ bt,
    const float* __restrict__ img)
{
    int bm = blockIdx.x;
    int b  = bm / NMASK, mm = bm % NMASK;
    int n  = midx[b * NMASK + mm];
    const float* e = xenc + ((size_t)(b * NTOK + n)) * DIM;
    int w = threadIdx.x >> 5, lane = threadIdx.x & 31;

    float acc = 0.f;
    for (int k = lane; k < DIM; k += 32) acc += e[k] * Wt[(size_t)k * PD + w];
    #pragma unroll
    for (int o = 16; o > 0; o >>= 1) acc += __shfl_xor_sync(0xffffffffu, acc, o);

    if (lane == 0) {
        float pred = acc + bt[w];
        int hh = n / WSEG, ws = n % WSEG;
        int p = w / NC, c = w % NC;
        float patch = img[(((size_t)b * NC + c) * HH + hh) * WW + ws * PP + p];
        atomicAdd(&g_sum, (double)fabsf(pred - patch));
    }
}

__global__ void fin_k(float* __restrict__ out) {
    // mean over (B*NM*PD)=43200 elements, then / NM
    out[0] = (float)(g_sum / (43200.0 * 900.0));
}

// ---------------- launch ----------------
extern "C" void kernel_launch(void* const* d_in, const int* in_sizes, int n_in,
                              void* d_out, int out_size)
{
    const float* img        = (const float*)d_in[0];
    const float* pos_table  = (const float*)d_in[1];
    const float* val_table  = (const float*)d_in[2];
    const float* patch_W    = (const float*)d_in[3];
    const float* patch_b    = (const float*)d_in[4];
    const float* mask_token = (const float*)d_in[5];
    const float* ln1_s      = (const float*)d_in[6];
    const float* ln1_b      = (const float*)d_in[7];
    const float* Wqkv       = (const float*)d_in[8];
    const float* bqkv       = (const float*)d_in[9];
    const float* Wo         = (const float*)d_in[10];
    const float* bo         = (const float*)d_in[11];
    const float* ln2_s      = (const float*)d_in[12];
    const float* ln2_b      = (const float*)d_in[13];
    const float* W1         = (const float*)d_in[14];
    const float* b1         = (const float*)d_in[15];
    const float* W2         = (const float*)d_in[16];
    const float* b2         = (const float*)d_in[17];
    const float* Wt         = (const float*)d_in[18];
    const float* bt         = (const float*)d_in[19];
    const int*   vlen       = (const int*)d_in[20];
    const int*   midx       = (const int*)d_in[21];

    float *px, *ph, *pqkv, *pao, *pmlp;
    cudaGetSymbolAddress((void**)&px,   g_x);
    cudaGetSymbolAddress((void**)&ph,   g_h);
    cudaGetSymbolAddress((void**)&pqkv, g_qkv);
    cudaGetSymbolAddress((void**)&pao,  g_ao);
    cudaGetSymbolAddress((void**)&pmlp, g_mlp);

    zero_k<<<(MTOK + 255) / 256, 256>>>();
    scat_k<<<(BATCH * NMASK + 255) / 256, 256>>>(midx);
    build_x_k<<<dim3(NTOK, BATCH), 128>>>(img, pos_table, val_table, patch_W,
                                          patch_b, mask_token, vlen);

    const int gy = (MTOK + BM - 1) / BM;  // 113
    for (int l = 0; l < LAYERS; l++) {
        ln_k<<<MTOK, 256>>>(px, ln1_s + l * DIM, ln1_b + l * DIM, ph);
        gemm_k<0><<<dim3(3 * DIM / BN, gy), 256>>>(
            ph, Wqkv + (size_t)l * DIM * 3 * DIM, bqkv + (size_t)l * 3 * DIM,
            nullptr, pqkv, MTOK, 3 * DIM, DIM);
        attn_k<<<dim3((NTOK + 127) / 128, NHEAD, BATCH), 128>>>(pqkv, pao);
        gemm_k<2><<<dim3(DIM / BN, gy), 256>>>(
            pao, Wo + (size_t)l * DIM * DIM, bo + (size_t)l * DIM,
            px, px, MTOK, DIM, DIM);
        ln_k<<<MTOK, 256>>>(px, ln2_s + l * DIM, ln2_b + l * DIM, ph);
        gemm_k<1><<<dim3(MLPD / BN, gy), 256>>>(
            ph, W1 + (size_t)l * DIM * MLPD, b1 + (size_t)l * MLPD,
            nullptr, pmlp, MTOK, MLPD, DIM);
        gemm_k<2><<<dim3(DIM / BN, gy), 256>>>(
            pmlp, W2 + (size_t)l * MLPD * DIM, b2 + (size_t)l * DIM,
            px, px, MTOK, DIM, MLPD);
    }

    loss_k<<<BATCH * NMASK, 192>>>(px, midx, Wt, bt, img);
    fin_k<<<1, 1>>>((float*)d_out);
}

// round 3
// speedup vs baseline: 1.6380x; 1.6380x over previous
#include <cuda_runtime.h>
#include <cuda_bf16.h>
#include <math.h>
#include <cstdint>

// ---------------- problem constants ----------------
#define BATCH   8
#define NC      3
#define HH      24
#define WW      150
#define PP      2
#define WSEG    75
#define NTOK    1800
#define PD      6
#define DIM     512
#define LAYERS  4
#define NHEAD   8
#define DHEAD   64
#define MLPD    2048
#define NMASK   900
#define MTOK    (BATCH*NTOK) // 14400
#define SCALE   0.125f

// ---------------- scratch (device globals; allocation-free) ----------------
__device__ __align__(128) float          g_x   [(size_t)MTOK * DIM];
__device__ __align__(128) float          g_qkv [(size_t)MTOK * 3 * DIM];
__device__ __align__(128) __nv_bfloat16  g_hb  [(size_t)MTOK * DIM];
__device__ __align__(128) __nv_bfloat16  g_aob [(size_t)MTOK * DIM];
__device__ __align__(128) __nv_bfloat16  g_gel [(size_t)MTOK * MLPD];
__device__ __align__(128) __nv_bfloat16  g_wt  [(size_t)12582912];   // transposed bf16 weights
__device__ int    g_mask[MTOK];
__device__ double g_sum;

// weight-transpose layout (per layer block of 3145728 bf16)
#define WT_LSTRIDE 3145728
#define WT_QKV     0
#define WT_O       786432
#define WT_W1      1048576
#define WT_W2      2097152

// ---------------- helpers ----------------
__device__ __forceinline__ uint32_t smem_to_u32(const void* p) {
    uint32_t a;
    asm("{ .reg .u64 t; cvta.to.shared.u64 t, %1; cvt.u32.u64 %0, t; }" : "=r"(a) : "l"(p));
    return a;
}
__device__ __forceinline__ void ldsm_x4(uint32_t* r, uint32_t addr) {
    asm volatile("ldmatrix.sync.aligned.m8n8.x4.shared.b16 {%0,%1,%2,%3}, [%4];"
        : "=r"(r[0]), "=r"(r[1]), "=r"(r[2]), "=r"(r[3]) : "r"(addr));
}
__device__ __forceinline__ void mma16816(float* d, const uint32_t* a, const uint32_t* b) {
    asm volatile(
        "mma.sync.aligned.m16n8k16.row.col.f32.bf16.bf16.f32 "
        "{%0,%1,%2,%3}, {%4,%5,%6,%7}, {%8,%9}, {%0,%1,%2,%3};"
        : "+f"(d[0]), "+f"(d[1]), "+f"(d[2]), "+f"(d[3])
        : "r"(a[0]), "r"(a[1]), "r"(a[2]), "r"(a[3]), "r"(b[0]), "r"(b[1]));
}
__device__ __forceinline__ float gelu_tanh(float x) {
    const float c = 0.7978845608028654f;
    float t = tanhf(c * (x + 0.044715f * x * x * x));
    return 0.5f * x * (1.0f + t);
}

// ---------------- setup kernels ----------------
__global__ void zero_k() {
    int i = blockIdx.x * 256 + threadIdx.x;
    if (i < MTOK) g_mask[i] = 0;
    if (i == 0)   g_sum = 0.0;
}
__global__ void scat_k(const int* __restrict__ midx) {
    int i = blockIdx.x * 256 + threadIdx.x;
    if (i < BATCH * NMASK) g_mask[(i / NMASK) * NTOK + midx[i]] = 1;
}

__global__ __launch_bounds__(128) void build_x_k(
    const float* __restrict__ img, const float* __restrict__ pos_table,
    const float* __restrict__ val_table, const float* __restrict__ patch_W,
    const float* __restrict__ patch_b, const float* __restrict__ mask_token,
    const int* __restrict__ valid_length)
{
    int n = blockIdx.x, b = blockIdx.y, t = threadIdx.x;
    __shared__ float pv[PD];
    __shared__ int sm_mask, sm_seg;
    int hh = n / WSEG, ws = n % WSEG;
    if (t < PD) {
        int p = t / NC, c = t % NC;
        pv[t] = img[(((size_t)b * NC + c) * HH + hh) * WW + ws * PP + p];
    } else if (t == 8) {
        sm_mask = g_mask[b * NTOK + n];
    } else if (t == 9) {
        int vl = valid_length[b];
        if (vl == 150) vl = 149;
        int nv = (vl + 1) >> 1;
        sm_seg = (ws < nv) ? 1 : 0;
    }
    __syncthreads();
    float p0 = pv[0], p1 = pv[1], p2 = pv[2], p3 = pv[3], p4 = pv[4], p5 = pv[5];
    int msk = sm_mask, seg = sm_seg;
    size_t rowo = ((size_t)(b * NTOK + n)) * DIM;
    for (int d = t; d < DIM; d += 128) {
        float pos = pos_table[(size_t)(n + 1) * DIM + d] + val_table[(size_t)seg * DIM + d];
        float v;
        if (msk) v = mask_token[d] + pos;
        else {
            v = patch_b[d]
              + p0 * patch_W[0 * DIM + d] + p1 * patch_W[1 * DIM + d]
              + p2 * patch_W[2 * DIM + d] + p3 * patch_W[3 * DIM + d]
              + p4 * patch_W[4 * DIM + d] + p5 * patch_W[5 * DIM + d];
            v += pos;
        }
        g_x[rowo + d] = v;
    }
}

// ---------------- weight transpose: W[K,N] fp32 -> WT[N,K] bf16 ----------------
__global__ __launch_bounds__(256) void tr_k(const float* __restrict__ W,
                                            __nv_bfloat16* __restrict__ WT, int K, int N)
{
    __shared__ float t[32][33];
    int n0 = blockIdx.x * 32, k0 = blockIdx.y * 32;
    int tx = threadIdx.x & 31, ty = threadIdx.x >> 5;
    #pragma unroll
    for (int i = 0; i < 4; i++) {
        int k = ty * 4 + i;
        t[k][tx] = W[(size_t)(k0 + k) * N + n0 + tx];
    }
    __syncthreads();
    #pragma unroll
    for (int i = 0; i < 4; i++) {
        int n = ty * 4 + i;
        WT[(size_t)(n0 + n) * K + k0 + tx] = __float2bfloat16(t[tx][n]);
    }
}

// ---------------- layernorm (fp32 in -> bf16 out) ----------------
__global__ __launch_bounds__(256) void ln_k(
    const float* __restrict__ x, const float* __restrict__ gam,
    const float* __restrict__ bet, __nv_bfloat16* __restrict__ out)
{
    int r = blockIdx.x, t = threadIdx.x;
    const float* xr = x + (size_t)r * DIM;
    float v0 = xr[t], v1 = xr[t + 256];
    float sum = v0 + v1, sq = v0 * v0 + v1 * v1;
    __shared__ float sh[64];
    #pragma unroll
    for (int o = 16; o > 0; o >>= 1) {
        sum += __shfl_xor_sync(0xffffffffu, sum, o);
        sq  += __shfl_xor_sync(0xffffffffu, sq,  o);
    }
    int warp = t >> 5, lane = t & 31;
    if (lane == 0) { sh[warp] = sum; sh[warp + 32] = sq; }
    __syncthreads();
    if (t == 0) {
        float ts = 0.f, tq = 0.f;
        #pragma unroll
        for (int i = 0; i < 8; i++) { ts += sh[i]; tq += sh[32 + i]; }
        float mean = ts * (1.0f / DIM);
        float var  = tq * (1.0f / DIM) - mean * mean;
        sh[0] = mean; sh[1] = rsqrtf(var + 1e-5f);
    }
    __syncthreads();
    float mean = sh[0], rstd = sh[1];
    out[(size_t)r * DIM + t]       = __float2bfloat16((v0 - mean) * rstd * gam[t]       + bet[t]);
    out[(size_t)r * DIM + t + 256] = __float2bfloat16((v1 - mean) * rstd * gam[t + 256] + bet[t + 256]);
}

// ---------------- HMMA bf16 GEMM, 128x128x32 tiles, double-buffered ----------------
// C[M,N] = epi( A[M,K](bf16,K-major) @ B[N,K](bf16,K-major)^T + bias )
// EPI: 0=bias, 1=bias+gelu, 2=bias+residual(R fp32). OUTB: 0=fp32, 1=bf16.
#define BM 128
#define BN 128
#define BK 32
#define LDP 40   // padded row stride in elements (80B): conflict-free ldmatrix

template <int EPI, int OUTB>
__global__ __launch_bounds__(256) void mma_gemm_k(
    const __nv_bfloat16* __restrict__ A, const __nv_bfloat16* __restrict__ B,
    const float* __restrict__ bias, const float* __restrict__ R,
    void* __restrict__ Cout, int M, int N, int K)
{
    __shared__ __align__(16) __nv_bfloat16 As[2][BM * LDP];
    __shared__ __align__(16) __nv_bfloat16 Bs[2][BN * LDP];

    const int tid = threadIdx.x, lane = tid & 31, wid = tid >> 5;
    const int wm = wid >> 2, wn = wid & 3;          // warp grid 2(m) x 4(n)
    const int m0 = blockIdx.y * BM, n0 = blockIdx.x * BN;

    // global staging: each thread owns 32B of one row (A and B)
    const int lrow = tid >> 1;
    const int lcol = (tid & 1) * 16;
    const bool aok = (m0 + lrow) < M;
    const __nv_bfloat16* Ag = A + (size_t)(m0 + lrow) * K + lcol;
    const __nv_bfloat16* Bg = B + (size_t)(n0 + lrow) * K + lcol;

    float acc[4][4][4];
    #pragma unroll
    for (int i = 0; i < 4; i++)
        #pragma unroll
        for (int j = 0; j < 4; j++)
            #pragma unroll
            for (int q = 0; q < 4; q++) acc[i][j][q] = 0.f;

    const uint32_t sAu = smem_to_u32(As);
    const uint32_t sBu = smem_to_u32(Bs);

    // ldmatrix lane address components
    const int a_r = wm * 64 + (lane & 15);
    const int a_c = (lane >> 4) * 8;
    const int b_r = wn * 32 + (lane & 7) + ((lane >> 4) << 3);
    const int b_c = ((lane >> 3) & 1) * 8;

    const int NK = K >> 5;
    uint4 ra0, ra1, rb0, rb1;
    const uint4 zz = make_uint4(0u, 0u, 0u, 0u);

    // preload tile 0 into buffer 0
    ra0 = aok ? *(const uint4*)(Ag)     : zz;
    ra1 = aok ? *(const uint4*)(Ag + 8) : zz;
    rb0 = *(const uint4*)(Bg);
    rb1 = *(const uint4*)(Bg + 8);
    *(uint4*)&As[0][lrow * LDP + lcol]     = ra0;
    *(uint4*)&As[0][lrow * LDP + lcol + 8] = ra1;
    *(uint4*)&Bs[0][lrow * LDP + lcol]     = rb0;
    *(uint4*)&Bs[0][lrow * LDP + lcol + 8] = rb1;
    __syncthreads();

    for (int kt = 0; kt < NK; kt++) {
        const int buf = kt & 1;
        if (kt + 1 < NK) {
            const __nv_bfloat16* An = Ag + (kt + 1) * BK;
            const __nv_bfloat16* Bn = Bg + (kt + 1) * BK;
            ra0 = aok ? *(const uint4*)(An)     : zz;
            ra1 = aok ? *(const uint4*)(An + 8) : zz;
            rb0 = *(const uint4*)(Bn);
            rb1 = *(const uint4*)(Bn + 8);
        }
        const uint32_t sa = sAu + buf * (BM * LDP * 2);
        const uint32_t sb = sBu + buf * (BN * LDP * 2);
        #pragma unroll
        for (int ks = 0; ks < 2; ks++) {
            uint32_t af[4][4], bf2[2][4];
            #pragma unroll
            for (int mi = 0; mi < 4; mi++) {
                uint32_t ad = sa + (uint32_t)(((a_r + mi * 16) * LDP) + ks * 16 + a_c) * 2u;
                ldsm_x4(af[mi], ad);
            }
            #pragma unroll
            for (int nj = 0; nj < 2; nj++) {
                uint32_t bd = sb + (uint32_t)(((b_r + nj * 16) * LDP) + ks * 16 + b_c) * 2u;
                ldsm_x4(bf2[nj], bd);
            }
            #pragma unroll
            for (int mi = 0; mi < 4; mi++)
                #pragma unroll
                for (int nj = 0; nj < 4; nj++)
                    mma16816(acc[mi][nj], af[mi], &bf2[nj >> 1][(nj & 1) * 2]);
        }
        if (kt + 1 < NK) {
            const int nb = buf ^ 1;
            *(uint4*)&As[nb][lrow * LDP + lcol]     = ra0;
            *(uint4*)&As[nb][lrow * LDP + lcol + 8] = ra1;
            *(uint4*)&Bs[nb][lrow * LDP + lcol]     = rb0;
            *(uint4*)&Bs[nb][lrow * LDP + lcol + 8] = rb1;
            __syncthreads();
        }
    }

    // epilogue
    const int r_lane = (lane >> 2);
    const int c_lane = (lane & 3) * 2;
    #pragma unroll
    for (int mi = 0; mi < 4; mi++) {
        const int r0 = m0 + wm * 64 + mi * 16 + r_lane;
        #pragma unroll
        for (int half = 0; half < 2; half++) {
            const int row = r0 + half * 8;
            if (row >= M) continue;
            #pragma unroll
            for (int nj = 0; nj < 4; nj++) {
                const int c = n0 + wn * 32 + nj * 8 + c_lane;
                float v0 = acc[mi][nj][half * 2 + 0] + bias[c];
                float v1 = acc[mi][nj][half * 2 + 1] + bias[c + 1];
                if (EPI == 1) { v0 = gelu_tanh(v0); v1 = gelu_tanh(v1); }
                if (EPI == 2) {
                    float2 rr = *(const float2*)(R + (size_t)row * N + c);
                    v0 += rr.x; v1 += rr.y;
                }
                if (OUTB) {
                    *(__nv_bfloat162*)((__nv_bfloat16*)Cout + (size_t)row * N + c) =
                        __floats2bfloat162_rn(v0, v1);
                } else {
                    *(float2*)((float*)Cout + (size_t)row * N + c) = make_float2(v0, v1);
                }
            }
        }
    }
}

// ---------------- flash attention (fp32 SIMT, bf16 out) ----------------
__global__ __launch_bounds__(128) void attn_k(const float* __restrict__ qkv,
                                              __nv_bfloat16* __restrict__ out)
{
    int b = blockIdx.z, h = blockIdx.y;
    int q = blockIdx.x * 128 + threadIdx.x;
    int tid = threadIdx.x;
    bool qvalid = (q < NTOK);

    __shared__ __align__(16) float Ks[16][DHEAD];
    __shared__ __align__(16) float Vs[16][DHEAD];

    float qreg[DHEAD];
    {
        const float* qptr = qkv + ((size_t)(b * NTOK + (qvalid ? q : 0))) * (3 * DIM) + h * DHEAD;
        #pragma unroll
        for (int d = 0; d < DHEAD; d++) qreg[d] = qptr[d] * SCALE;
    }

    float m = -1e30f, l = 0.f;
    float o[DHEAD];
    #pragma unroll
    for (int d = 0; d < DHEAD; d++) o[d] = 0.f;

    for (int t0 = 0; t0 < NTOK; t0 += 16) {
        __syncthreads();
        #pragma unroll
        for (int i = 0; i < 2; i++) {
            int f  = tid * 2 + i;
            int j  = f >> 4;
            int dc = (f & 15) * 4;
            int kr = t0 + j;
            float4 kv, vv;
            if (kr < NTOK) {
                const float* base = qkv + ((size_t)(b * NTOK + kr)) * (3 * DIM) + h * DHEAD;
                kv = *(const float4*)(base + DIM + dc);
                vv = *(const float4*)(base + 2 * DIM + dc);
            } else {
                kv = make_float4(0.f, 0.f, 0.f, 0.f);
                vv = kv;
            }
            *(float4*)&Ks[j][dc] = kv;
            *(float4*)&Vs[j][dc] = vv;
        }
        __syncthreads();

        int nk = NTOK - t0; if (nk > 16) nk = 16;
        float s[16];
        #pragma unroll
        for (int j = 0; j < 16; j++) {
            const float4* K4 = (const float4*)Ks[j];
            float a0 = 0.f, a1 = 0.f, a2 = 0.f, a3 = 0.f;
            #pragma unroll
            for (int d4 = 0; d4 < 16; d4++) {
                float4 kv = K4[d4];
                a0 += qreg[4 * d4 + 0] * kv.x;
                a1 += qreg[4 * d4 + 1] * kv.y;
                a2 += qreg[4 * d4 + 2] * kv.z;
                a3 += qreg[4 * d4 + 3] * kv.w;
            }
            s[j] = (a0 + a1) + (a2 + a3);
        }
        float mt = -1e30f;
        for (int j = 0; j < nk; j++) mt = fmaxf(mt, s[j]);
        float mn = fmaxf(m, mt);
        float corr = __expf(m - mn);
        l *= corr;
        #pragma unroll
        for (int d = 0; d < DHEAD; d++) o[d] *= corr;
        for (int j = 0; j < nk; j++) {
            float p = __expf(s[j] - mn);
            l += p;
            const float4* V4 = (const float4*)Vs[j];
            #pragma unroll
            for (int d4 = 0; d4 < 16; d4++) {
                float4 vv = V4[d4];
                o[4 * d4 + 0] += p * vv.x;
                o[4 * d4 + 1] += p * vv.y;
                o[4 * d4 + 2] += p * vv.z;
                o[4 * d4 + 3] += p * vv.w;
            }
        }
        m = mn;
    }

    if (qvalid) {
        float inv = 1.0f / l;
        __nv_bfloat162* op = (__nv_bfloat162*)(out + ((size_t)(b * NTOK + q)) * DIM + h * DHEAD);
        #pragma unroll
        for (int d2 = 0; d2 < 32; d2++)
            op[d2] = __floats2bfloat162_rn(o[2 * d2] * inv, o[2 * d2 + 1] * inv);
    }
}

// ---------------- masked-patch prediction + L1 loss ----------------
__global__ __launch_bounds__(192) void loss_k(
    const float* __restrict__ xenc, const int* __restrict__ midx,
    const float* __restrict__ Wt, const float* __restrict__ bt,
    const float* __restrict__ img)
{
    int bm = blockIdx.x;
    int b  = bm / NMASK, mm = bm % NMASK;
    int n  = midx[b * NMASK + mm];
    const float* e = xenc + ((size_t)(b * NTOK + n)) * DIM;
    int w = threadIdx.x >> 5, lane = threadIdx.x & 31;

    float acc = 0.f;
    for (int k = lane; k < DIM; k += 32) acc += e[k] * Wt[(size_t)k * PD + w];
    #pragma unroll
    for (int o = 16; o > 0; o >>= 1) acc += __shfl_xor_sync(0xffffffffu, acc, o);

    if (lane == 0) {
        float pred = acc + bt[w];
        int hh = n / WSEG, ws = n % WSEG;
        int p = w / NC, c = w % NC;
        float patch = img[(((size_t)b * NC + c) * HH + hh) * WW + ws * PP + p];
        atomicAdd(&g_sum, (double)fabsf(pred - patch));
    }
}

__global__ void fin_k(float* __restrict__ out) {
    out[0] = (float)(g_sum / (43200.0 * 900.0));
}

// ---------------- launch ----------------
extern "C" void kernel_launch(void* const* d_in, const int* in_sizes, int n_in,
                              void* d_out, int out_size)
{
    const float* img        = (const float*)d_in[0];
    const float* pos_table  = (const float*)d_in[1];
    const float* val_table  = (const float*)d_in[2];
    const float* patch_W    = (const float*)d_in[3];
    const float* patch_b    = (const float*)d_in[4];
    const float* mask_token = (const float*)d_in[5];
    const float* ln1_s      = (const float*)d_in[6];
    const float* ln1_b      = (const float*)d_in[7];
    const float* Wqkv       = (const float*)d_in[8];
    const float* bqkv       = (const float*)d_in[9];
    const float* Wo         = (const float*)d_in[10];
    const float* bo         = (const float*)d_in[11];
    const float* ln2_s      = (const float*)d_in[12];
    const float* ln2_b      = (const float*)d_in[13];
    const float* W1         = (const float*)d_in[14];
    const float* b1         = (const float*)d_in[15];
    const float* W2         = (const float*)d_in[16];
    const float* b2         = (const float*)d_in[17];
    const float* Wt         = (const float*)d_in[18];
    const float* bt         = (const float*)d_in[19];
    const int*   vlen       = (const int*)d_in[20];
    const int*   midx       = (const int*)d_in[21];

    float *px, *pqkv;
    __nv_bfloat16 *phb, *paob, *pgel, *pwt;
    cudaGetSymbolAddress((void**)&px,   g_x);
    cudaGetSymbolAddress((void**)&pqkv, g_qkv);
    cudaGetSymbolAddress((void**)&phb,  g_hb);
    cudaGetSymbolAddress((void**)&paob, g_aob);
    cudaGetSymbolAddress((void**)&pgel, g_gel);
    cudaGetSymbolAddress((void**)&pwt,  g_wt);

    zero_k<<<(MTOK + 255) / 256, 256>>>();
    scat_k<<<(BATCH * NMASK + 255) / 256, 256>>>(midx);
    build_x_k<<<dim3(NTOK, BATCH), 128>>>(img, pos_table, val_table, patch_W,
                                          patch_b, mask_token, vlen);

    // transpose + bf16-convert all weights
    for (int l = 0; l < LAYERS; l++) {
        __nv_bfloat16* wl = pwt + (size_t)l * WT_LSTRIDE;
        tr_k<<<dim3(1536 / 32, 512 / 32),  256>>>(Wqkv + (size_t)l * 512 * 1536, wl + WT_QKV, 512, 1536);
        tr_k<<<dim3(512 / 32,  512 / 32),  256>>>(Wo   + (size_t)l * 512 * 512,  wl + WT_O,   512, 512);
        tr_k<<<dim3(2048 / 32, 512 / 32),  256>>>(W1   + (size_t)l * 512 * 2048, wl + WT_W1,  512, 2048);
        tr_k<<<dim3(512 / 32,  2048 / 32), 256>>>(W2   + (size_t)l * 2048 * 512, wl + WT_W2, 2048, 512);
    }

    const int gy = (MTOK + BM - 1) / BM;  // 113
    for (int l = 0; l < LAYERS; l++) {
        __nv_bfloat16* wl = pwt + (size_t)l * WT_LSTRIDE;
        ln_k<<<MTOK, 256>>>(px, ln1_s + l * DIM, ln1_b + l * DIM, phb);
        mma_gemm_k<0,0><<<dim3(12, gy), 256>>>(
            phb, wl + WT_QKV, bqkv + (size_t)l * 3 * DIM, nullptr, pqkv, MTOK, 3 * DIM, DIM);
        attn_k<<<dim3((NTOK + 127) / 128, NHEAD, BATCH), 128>>>(pqkv, paob);
        mma_gemm_k<2,0><<<dim3(4, gy), 256>>>(
            paob, wl + WT_O, bo + (size_t)l * DIM, px, px, MTOK, DIM, DIM);
        ln_k<<<MTOK, 256>>>(px, ln2_s + l * DIM, ln2_b + l * DIM, phb);
        mma_gemm_k<1,1><<<dim3(16, gy), 256>>>(
            phb, wl + WT_W1, b1 + (size_t)l * MLPD, nullptr, pgel, MTOK, MLPD, DIM);
        mma_gemm_k<2,0><<<dim3(4, gy), 256>>>(
            pgel, wl + WT_W2, b2 + (size_t)l * DIM, px, px, MTOK, DIM, MLPD);
    }

    loss_k<<<BATCH * NMASK, 192>>>(px, midx, Wt, bt, img);
    fin_k<<<1, 1>>>((float*)d_out);
}

// round 4
// speedup vs baseline: 7.4874x; 4.5710x over previous
#include <cuda_runtime.h>
#include <cuda_bf16.h>
#include <math.h>
#include <cstdint>

// ---------------- problem constants ----------------
#define BATCH   8
#define NC      3
#define HH      24
#define WW      150
#define PP      2
#define WSEG    75
#define NTOK    1800
#define PD      6
#define DIM     512
#define LAYERS  4
#define NHEAD   8
#define DHEAD   64
#define MLPD    2048
#define NMASK   900
#define MTOK    (BATCH*NTOK) // 14400
#define SCALE   0.125f

// ---------------- scratch (device globals; allocation-free) ----------------
__device__ __align__(128) float          g_x   [(size_t)MTOK * DIM];
__device__ __align__(128) __nv_bfloat16  g_qkvb[(size_t)MTOK * 3 * DIM];
__device__ __align__(128) __nv_bfloat16  g_hb  [(size_t)MTOK * DIM];
__device__ __align__(128) __nv_bfloat16  g_aob [(size_t)MTOK * DIM];
__device__ __align__(128) __nv_bfloat16  g_gel [(size_t)MTOK * MLPD];
__device__ __align__(128) __nv_bfloat16  g_wt  [(size_t)12582912];   // transposed bf16 weights
__device__ int    g_mask[MTOK];
__device__ double g_sum;

// weight-transpose layout (per layer block of 3145728 bf16)
#define WT_LSTRIDE 3145728
#define WT_QKV     0
#define WT_O       786432
#define WT_W1      1048576
#define WT_W2      2097152

// ---------------- helpers ----------------
__device__ __forceinline__ uint32_t smem_to_u32(const void* p) {
    uint32_t a;
    asm("{ .reg .u64 t; cvta.to.shared.u64 t, %1; cvt.u32.u64 %0, t; }" : "=r"(a) : "l"(p));
    return a;
}
__device__ __forceinline__ void ldsm_x4(uint32_t* r, uint32_t addr) {
    asm volatile("ldmatrix.sync.aligned.m8n8.x4.shared.b16 {%0,%1,%2,%3}, [%4];"
        : "=r"(r[0]), "=r"(r[1]), "=r"(r[2]), "=r"(r[3]) : "r"(addr));
}
__device__ __forceinline__ void mma16816(float* d, const uint32_t* a, const uint32_t* b) {
    asm volatile(
        "mma.sync.aligned.m16n8k16.row.col.f32.bf16.bf16.f32 "
        "{%0,%1,%2,%3}, {%4,%5,%6,%7}, {%8,%9}, {%0,%1,%2,%3};"
        : "+f"(d[0]), "+f"(d[1]), "+f"(d[2]), "+f"(d[3])
        : "r"(a[0]), "r"(a[1]), "r"(a[2]), "r"(a[3]), "r"(b[0]), "r"(b[1]));
}
__device__ __forceinline__ void cp16(uint32_t dst, const void* src, uint32_t sz) {
    asm volatile("cp.async.ca.shared.global [%0], [%1], 16, %2;"
        :: "r"(dst), "l"(src), "r"(sz) : "memory");
}
#define CP_COMMIT() asm volatile("cp.async.commit_group;" ::: "memory")
#define CP_WAIT0()  asm volatile("cp.async.wait_group 0;"  ::: "memory")
#define CP_WAIT1()  asm volatile("cp.async.wait_group 1;"  ::: "memory")

__device__ __forceinline__ uint32_t packbf(float a, float b) {
    __nv_bfloat162 t = __floats2bfloat162_rn(a, b);
    return *(uint32_t*)&t;
}
__device__ __forceinline__ float gelu_tanh(float x) {
    const float c = 0.7978845608028654f;
    float t = tanhf(c * (x + 0.044715f * x * x * x));
    return 0.5f * x * (1.0f + t);
}

// ---------------- setup kernels ----------------
__global__ void zero_k() {
    int i = blockIdx.x * 256 + threadIdx.x;
    if (i < MTOK) g_mask[i] = 0;
    if (i == 0)   g_sum = 0.0;
}
__global__ void scat_k(const int* __restrict__ midx) {
    int i = blockIdx.x * 256 + threadIdx.x;
    if (i < BATCH * NMASK) g_mask[(i / NMASK) * NTOK + midx[i]] = 1;
}

__global__ __launch_bounds__(128) void build_x_k(
    const float* __restrict__ img, const float* __restrict__ pos_table,
    const float* __restrict__ val_table, const float* __restrict__ patch_W,
    const float* __restrict__ patch_b, const float* __restrict__ mask_token,
    const int* __restrict__ valid_length)
{
    int n = blockIdx.x, b = blockIdx.y, t = threadIdx.x;
    __shared__ float pv[PD];
    __shared__ int sm_mask, sm_seg;
    int hh = n / WSEG, ws = n % WSEG;
    if (t < PD) {
        int p = t / NC, c = t % NC;
        pv[t] = img[(((size_t)b * NC + c) * HH + hh) * WW + ws * PP + p];
    } else if (t == 8) {
        sm_mask = g_mask[b * NTOK + n];
    } else if (t == 9) {
        int vl = valid_length[b];
        if (vl == 150) vl = 149;
        int nv = (vl + 1) >> 1;
        sm_seg = (ws < nv) ? 1 : 0;
    }
    __syncthreads();
    float p0 = pv[0], p1 = pv[1], p2 = pv[2], p3 = pv[3], p4 = pv[4], p5 = pv[5];
    int msk = sm_mask, seg = sm_seg;
    size_t rowo = ((size_t)(b * NTOK + n)) * DIM;
    for (int d = t; d < DIM; d += 128) {
        float pos = pos_table[(size_t)(n + 1) * DIM + d] + val_table[(size_t)seg * DIM + d];
        float v;
        if (msk) v = mask_token[d] + pos;
        else {
            v = patch_b[d]
              + p0 * patch_W[0 * DIM + d] + p1 * patch_W[1 * DIM + d]
              + p2 * patch_W[2 * DIM + d] + p3 * patch_W[3 * DIM + d]
              + p4 * patch_W[4 * DIM + d] + p5 * patch_W[5 * DIM + d];
            v += pos;
        }
        g_x[rowo + d] = v;
    }
}

// ---------------- weight transpose: W[K,N] fp32 -> WT[N,K] bf16 ----------------
__global__ __launch_bounds__(256) void tr_k(const float* __restrict__ W,
                                            __nv_bfloat16* __restrict__ WT, int K, int N)
{
    __shared__ float t[32][33];
    int n0 = blockIdx.x * 32, k0 = blockIdx.y * 32;
    int tx = threadIdx.x & 31, ty = threadIdx.x >> 5;
    #pragma unroll
    for (int i = 0; i < 4; i++) {
        int k = ty * 4 + i;
        t[k][tx] = W[(size_t)(k0 + k) * N + n0 + tx];
    }
    __syncthreads();
    #pragma unroll
    for (int i = 0; i < 4; i++) {
        int n = ty * 4 + i;
        WT[(size_t)(n0 + n) * K + k0 + tx] = __float2bfloat16(t[tx][n]);
    }
}

// ---------------- layernorm (fp32 in -> bf16 out) ----------------
__global__ __launch_bounds__(256) void ln_k(
    const float* __restrict__ x, const float* __restrict__ gam,
    const float* __restrict__ bet, __nv_bfloat16* __restrict__ out)
{
    int r = blockIdx.x, t = threadIdx.x;
    const float* xr = x + (size_t)r * DIM;
    float v0 = xr[t], v1 = xr[t + 256];
    float sum = v0 + v1, sq = v0 * v0 + v1 * v1;
    __shared__ float sh[64];
    #pragma unroll
    for (int o = 16; o > 0; o >>= 1) {
        sum += __shfl_xor_sync(0xffffffffu, sum, o);
        sq  += __shfl_xor_sync(0xffffffffu, sq,  o);
    }
    int warp = t >> 5, lane = t & 31;
    if (lane == 0) { sh[warp] = sum; sh[warp + 32] = sq; }
    __syncthreads();
    if (t == 0) {
        float ts = 0.f, tq = 0.f;
        #pragma unroll
        for (int i = 0; i < 8; i++) { ts += sh[i]; tq += sh[32 + i]; }
        float mean = ts * (1.0f / DIM);
        float var  = tq * (1.0f / DIM) - mean * mean;
        sh[0] = mean; sh[1] = rsqrtf(var + 1e-5f);
    }
    __syncthreads();
    float mean = sh[0], rstd = sh[1];
    out[(size_t)r * DIM + t]       = __float2bfloat16((v0 - mean) * rstd * gam[t]       + bet[t]);
    out[(size_t)r * DIM + t + 256] = __float2bfloat16((v1 - mean) * rstd * gam[t + 256] + bet[t + 256]);
}

// ---------------- HMMA bf16 GEMM, 128x128x32 tiles, 3-stage cp.async ----------------
#define BM 128
#define BN 128
#define BK 32
#define LDP 40   // padded row stride (80B): 16B-aligned rows, conflict-free ldmatrix
#define GEMM_SMEM (6 * BM * LDP * 2)   // 61440

template <int EPI, int OUTB>
__global__ __launch_bounds__(256) void mma_gemm_k(
    const __nv_bfloat16* __restrict__ A, const __nv_bfloat16* __restrict__ B,
    const float* __restrict__ bias, const float* __restrict__ R,
    void* __restrict__ Cout, int M, int N, int K)
{
    extern __shared__ __align__(16) __nv_bfloat16 sm_g[];
    __nv_bfloat16* As = sm_g;
    __nv_bfloat16* Bs = sm_g + 3 * BM * LDP;

    const int tid = threadIdx.x, lane = tid & 31, wid = tid >> 5;
    const int wm = wid >> 2, wn = wid & 3;
    const int m0 = blockIdx.y * BM, n0 = blockIdx.x * BN;

    const uint32_t sAu = smem_to_u32(As);
    const uint32_t sBu = smem_to_u32(Bs);
    const uint32_t ABYT = BM * LDP * 2;

    float acc[4][4][4];
    #pragma unroll
    for (int i = 0; i < 4; i++)
        #pragma unroll
        for (int j = 0; j < 4; j++)
            #pragma unroll
            for (int q = 0; q < 4; q++) acc[i][j][q] = 0.f;

    const int NK = K >> 5;
    auto issue = [&](int kt, int st) {
        #pragma unroll
        for (int i = 0; i < 2; i++) {
            int ch = tid + i * 256;
            int row = ch >> 2, c8 = (ch & 3) * 8;
            uint32_t da = sAu + st * ABYT + (uint32_t)(row * LDP + c8) * 2;
            cp16(da, A + (size_t)(m0 + row) * K + kt * BK + c8, (m0 + row) < M ? 16u : 0u);
            uint32_t db = sBu + st * ABYT + (uint32_t)(row * LDP + c8) * 2;
            cp16(db, B + (size_t)(n0 + row) * K + kt * BK + c8, 16u);
        }
        CP_COMMIT();
    };
    issue(0, 0);
    issue(1, 1);

    const int a_r = wm * 64 + (lane & 15);
    const int a_c = (lane >> 4) * 8;
    const int b_r = wn * 32 + (lane & 7) + ((lane >> 4) << 3);
    const int b_c = ((lane >> 3) & 1) * 8;

    int st = 0;
    for (int kt = 0; kt < NK; kt++) {
        CP_WAIT1();
        __syncthreads();
        if (kt + 2 < NK) issue(kt + 2, (kt + 2) % 3);
        else CP_COMMIT();
        const uint32_t sa = sAu + st * ABYT;
        const uint32_t sb = sBu + st * ABYT;
        #pragma unroll
        for (int ks = 0; ks < 2; ks++) {
            uint32_t af[4][4], bf2[2][4];
            #pragma unroll
            for (int mi = 0; mi < 4; mi++)
                ldsm_x4(af[mi], sa + (uint32_t)(((a_r + mi * 16) * LDP) + ks * 16 + a_c) * 2u);
            #pragma unroll
            for (int nj = 0; nj < 2; nj++)
                ldsm_x4(bf2[nj], sb + (uint32_t)(((b_r + nj * 16) * LDP) + ks * 16 + b_c) * 2u);
            #pragma unroll
            for (int mi = 0; mi < 4; mi++)
                #pragma unroll
                for (int nj = 0; nj < 4; nj++)
                    mma16816(acc[mi][nj], af[mi], &bf2[nj >> 1][(nj & 1) * 2]);
        }
        st++; if (st == 3) st = 0;
    }

    // epilogue
    const int r_lane = (lane >> 2);
    const int c_lane = (lane & 3) * 2;
    #pragma unroll
    for (int mi = 0; mi < 4; mi++) {
        const int r0 = m0 + wm * 64 + mi * 16 + r_lane;
        #pragma unroll
        for (int half = 0; half < 2; half++) {
            const int row = r0 + half * 8;
            if (row >= M) continue;
            #pragma unroll
            for (int nj = 0; nj < 4; nj++) {
                const int c = n0 + wn * 32 + nj * 8 + c_lane;
                float v0 = acc[mi][nj][half * 2 + 0] + bias[c];
                float v1 = acc[mi][nj][half * 2 + 1] + bias[c + 1];
                if (EPI == 1) { v0 = gelu_tanh(v0); v1 = gelu_tanh(v1); }
                if (EPI == 2) {
                    float2 rr = *(const float2*)(R + (size_t)row * N + c);
                    v0 += rr.x; v1 += rr.y;
                }
                if (OUTB) {
                    *(__nv_bfloat162*)((__nv_bfloat16*)Cout + (size_t)row * N + c) =
                        __floats2bfloat162_rn(v0, v1);
                } else {
                    *(float2*)((float*)Cout + (size_t)row * N + c) = make_float2(v0, v1);
                }
            }
        }
    }
}

// ---------------- HMMA bf16 flash attention ----------------
// 64 queries/CTA (4 warps x m16), 64-key tiles, K via cp.async, V transposed on store.
#define BQ  64
#define BKV 64
#define KVP 72
#define NKT ((NTOK + BKV - 1) / BKV)   // 29

__global__ __launch_bounds__(128) void fattn_k(const __nv_bfloat16* __restrict__ qkv,
                                               __nv_bfloat16* __restrict__ out)
{
    const int b = blockIdx.z, h = blockIdx.y;
    const int q0 = blockIdx.x * BQ;
    const int tid = threadIdx.x, lane = tid & 31, wid = tid >> 5;
    const int qw = q0 + wid * 16;

    __shared__ __align__(16) __nv_bfloat16 KsS[2][BKV * KVP];
    __shared__ __align__(16) __nv_bfloat16 VtS[2][BKV * KVP];   // [dim][key]

    const size_t tokb = (size_t)b * NTOK;
    const size_t rstr = 3 * DIM;
    const int hb = h * DHEAD;
    const uint32_t ksu = smem_to_u32(KsS);
    const uint32_t vtu = smem_to_u32(VtS);
    const uint32_t KVBYT = BKV * KVP * 2;

    // Q fragments (scaled by 0.125 -- exact in bf16)
    uint32_t qa[4][4];
    {
        int r = lane >> 2, c = (lane & 3) * 2;
        #pragma unroll
        for (int ks = 0; ks < 4; ks++)
            #pragma unroll
            for (int p = 0; p < 4; p++) {
                int rr = qw + r + (p & 1) * 8;
                if (rr > NTOK - 1) rr = NTOK - 1;
                int cc = ks * 16 + (p >> 1) * 8 + c;
                __nv_bfloat162 v = *(const __nv_bfloat162*)(qkv + (tokb + rr) * rstr + hb + cc);
                float2 f = __bfloat1622float2(v);
                qa[ks][p] = packbf(f.x * SCALE, f.y * SCALE);
            }
    }

    float o[8][4];
    #pragma unroll
    for (int j = 0; j < 8; j++)
        #pragma unroll
        for (int q = 0; q < 4; q++) o[j][q] = 0.f;
    float m0v = -1e30f, m1v = -1e30f, l0 = 0.f, l1 = 0.f;

    uint4 vr[4];
    const uint4 zz = make_uint4(0u, 0u, 0u, 0u);
    auto stageK = [&](int kt, int bufi) {
        #pragma unroll
        for (int i = 0; i < 4; i++) {
            int ch = tid + i * 128;
            int row = ch >> 3, c16 = ch & 7;
            int kr = kt * BKV + row;
            uint32_t d = ksu + bufi * KVBYT + (uint32_t)(row * KVP + c16 * 8) * 2;
            const void* s = qkv + (tokb + (kr < NTOK ? kr : 0)) * rstr + DIM + hb + c16 * 8;
            cp16(d, s, kr < NTOK ? 16u : 0u);
        }
        CP_COMMIT();
    };
    auto loadV = [&](int kt) {
        int key = tid >> 1, dim0 = (tid & 1) * 32;
        int kr = kt * BKV + key;
        if (kr < NTOK) {
            const uint4* p = (const uint4*)(qkv + (tokb + kr) * rstr + 2 * DIM + hb + dim0);
            vr[0] = p[0]; vr[1] = p[1]; vr[2] = p[2]; vr[3] = p[3];
        } else { vr[0] = zz; vr[1] = zz; vr[2] = zz; vr[3] = zz; }
    };
    auto stsV = [&](int bufi) {
        int key = tid >> 1, dim0 = (tid & 1) * 32;
        const __nv_bfloat16* v16 = (const __nv_bfloat16*)vr;
        #pragma unroll
        for (int d = 0; d < 32; d++)
            VtS[bufi][(dim0 + d) * KVP + key] = v16[d];
    };

    stageK(0, 0);
    loadV(0);
    CP_WAIT0();
    stsV(0);
    __syncthreads();

    const int lr = (lane & 7) + ((lane >> 4) << 3);
    const int lc = ((lane >> 3) & 1) * 8;

    for (int kt = 0; kt < NKT; kt++) {
        const int bufi = kt & 1;
        if (kt + 1 < NKT) { stageK(kt + 1, bufi ^ 1); loadV(kt + 1); }

        // S = Q @ K^T (16 x 64 per warp)
        float s[8][4];
        #pragma unroll
        for (int j = 0; j < 8; j++)
            #pragma unroll
            for (int q = 0; q < 4; q++) s[j][q] = 0.f;
        const uint32_t kb = ksu + bufi * KVBYT;
        #pragma unroll
        for (int nj = 0; nj < 4; nj++)
            #pragma unroll
            for (int ks = 0; ks < 4; ks++) {
                uint32_t bf[4];
                ldsm_x4(bf, kb + (uint32_t)((nj * 16 + lr) * KVP + ks * 16 + lc) * 2u);
                mma16816(s[nj * 2],     qa[ks], bf);
                mma16816(s[nj * 2 + 1], qa[ks], bf + 2);
            }

        if (kt == NKT - 1) {
            #pragma unroll
            for (int j = 0; j < 8; j++) {
                int gc = kt * BKV + j * 8 + (lane & 3) * 2;
                if (gc     >= NTOK) { s[j][0] = -1e30f; s[j][2] = -1e30f; }
                if (gc + 1 >= NTOK) { s[j][1] = -1e30f; s[j][3] = -1e30f; }
            }
        }

        // online softmax
        float mt0 = -1e30f, mt1 = -1e30f;
        #pragma unroll
        for (int j = 0; j < 8; j++) {
            mt0 = fmaxf(mt0, fmaxf(s[j][0], s[j][1]));
            mt1 = fmaxf(mt1, fmaxf(s[j][2], s[j][3]));
        }
        mt0 = fmaxf(mt0, __shfl_xor_sync(0xffffffffu, mt0, 1));
        mt0 = fmaxf(mt0, __shfl_xor_sync(0xffffffffu, mt0, 2));
        mt1 = fmaxf(mt1, __shfl_xor_sync(0xffffffffu, mt1, 1));
        mt1 = fmaxf(mt1, __shfl_xor_sync(0xffffffffu, mt1, 2));
        float mn0 = fmaxf(m0v, mt0), mn1 = fmaxf(m1v, mt1);
        float c0 = __expf(m0v - mn0), c1 = __expf(m1v - mn1);
        l0 *= c0; l1 *= c1;
        #pragma unroll
        for (int j = 0; j < 8; j++) {
            float p0 = __expf(s[j][0] - mn0), p1 = __expf(s[j][1] - mn0);
            float p2 = __expf(s[j][2] - mn1), p3 = __expf(s[j][3] - mn1);
            l0 += p0 + p1; l1 += p2 + p3;
            s[j][0] = p0; s[j][1] = p1; s[j][2] = p2; s[j][3] = p3;
        }
        uint32_t pa[4][4];
        #pragma unroll
        for (int ks = 0; ks < 4; ks++) {
            pa[ks][0] = packbf(s[2 * ks][0],     s[2 * ks][1]);
            pa[ks][1] = packbf(s[2 * ks][2],     s[2 * ks][3]);
            pa[ks][2] = packbf(s[2 * ks + 1][0], s[2 * ks + 1][1]);
            pa[ks][3] = packbf(s[2 * ks + 1][2], s[2 * ks + 1][3]);
        }
        #pragma unroll
        for (int jj = 0; jj < 8; jj++) {
            o[jj][0] *= c0; o[jj][1] *= c0; o[jj][2] *= c1; o[jj][3] *= c1;
        }
        m0v = mn0; m1v = mn1;

        // O += P @ V   (Vt is [dim][key])
        const uint32_t vb = vtu + bufi * KVBYT;
        #pragma unroll
        for (int nj = 0; nj < 4; nj++)
            #pragma unroll
            for (int ks = 0; ks < 4; ks++) {
                uint32_t bf[4];
                ldsm_x4(bf, vb + (uint32_t)((nj * 16 + lr) * KVP + ks * 16 + lc) * 2u);
                mma16816(o[nj * 2],     pa[ks], bf);
                mma16816(o[nj * 2 + 1], pa[ks], bf + 2);
            }

        if (kt + 1 < NKT) {
            CP_WAIT0();
            stsV(bufi ^ 1);
        }
        __syncthreads();
    }

    l0 += __shfl_xor_sync(0xffffffffu, l0, 1);
    l0 += __shfl_xor_sync(0xffffffffu, l0, 2);
    l1 += __shfl_xor_sync(0xffffffffu, l1, 1);
    l1 += __shfl_xor_sync(0xffffffffu, l1, 2);
    float i0 = 1.f / l0, i1 = 1.f / l1;
    int r0 = qw + (lane >> 2), r1 = r0 + 8;
    int cb = hb + (lane & 3) * 2;
    if (r0 < NTOK) {
        __nv_bfloat16* op = out + (tokb + r0) * DIM;
        #pragma unroll
        for (int jj = 0; jj < 8; jj++)
            *(__nv_bfloat162*)(op + cb + jj * 8) = __floats2bfloat162_rn(o[jj][0] * i0, o[jj][1] * i0);
    }
    if (r1 < NTOK) {
        __nv_bfloat16* op = out + (tokb + r1) * DIM;
        #pragma unroll
        for (int jj = 0; jj < 8; jj++)
            *(__nv_bfloat162*)(op + cb + jj * 8) = __floats2bfloat162_rn(o[jj][2] * i1, o[jj][3] * i1);
    }
}

// ---------------- masked-patch prediction + L1 loss ----------------
__global__ __launch_bounds__(192) void loss_k(
    const float* __restrict__ xenc, const int* __restrict__ midx,
    const float* __restrict__ Wt, const float* __restrict__ bt,
    const float* __restrict__ img)
{
    int bm = blockIdx.x;
    int b  = bm / NMASK, mm = bm % NMASK;
    int n  = midx[b * NMASK + mm];
    const float* e = xenc + ((size_t)(b * NTOK + n)) * DIM;
    int w = threadIdx.x >> 5, lane = threadIdx.x & 31;

    float acc = 0.f;
    for (int k = lane; k < DIM; k += 32) acc += e[k] * Wt[(size_t)k * PD + w];
    #pragma unroll
    for (int o = 16; o > 0; o >>= 1) acc += __shfl_xor_sync(0xffffffffu, acc, o);

    if (lane == 0) {
        float pred = acc + bt[w];
        int hh = n / WSEG, ws = n % WSEG;
        int p = w / NC, c = w % NC;
        float patch = img[(((size_t)b * NC + c) * HH + hh) * WW + ws * PP + p];
        atomicAdd(&g_sum, (double)fabsf(pred - patch));
    }
}

__global__ void fin_k(float* __restrict__ out) {
    out[0] = (float)(g_sum / (43200.0 * 900.0));
}

// ---------------- launch ----------------
extern "C" void kernel_launch(void* const* d_in, const int* in_sizes, int n_in,
                              void* d_out, int out_size)
{
    const float* img        = (const float*)d_in[0];
    const float* pos_table  = (const float*)d_in[1];
    const float* val_table  = (const float*)d_in[2];
    const float* patch_W    = (const float*)d_in[3];
    const float* patch_b    = (const float*)d_in[4];
    const float* mask_token = (const float*)d_in[5];
    const float* ln1_s      = (const float*)d_in[6];
    const float* ln1_b      = (const float*)d_in[7];
    const float* Wqkv       = (const float*)d_in[8];
    const float* bqkv       = (const float*)d_in[9];
    const float* Wo         = (const float*)d_in[10];
    const float* bo         = (const float*)d_in[11];
    const float* ln2_s      = (const float*)d_in[12];
    const float* ln2_b      = (const float*)d_in[13];
    const float* W1         = (const float*)d_in[14];
    const float* b1         = (const float*)d_in[15];
    const float* W2         = (const float*)d_in[16];
    const float* b2         = (const float*)d_in[17];
    const float* Wt         = (const float*)d_in[18];
    const float* bt         = (const float*)d_in[19];
    const int*   vlen       = (const int*)d_in[20];
    const int*   midx       = (const int*)d_in[21];

    float* px;
    __nv_bfloat16 *pqkvb, *phb, *paob, *pgel, *pwt;
    cudaGetSymbolAddress((void**)&px,    g_x);
    cudaGetSymbolAddress((void**)&pqkvb, g_qkvb);
    cudaGetSymbolAddress((void**)&phb,   g_hb);
    cudaGetSymbolAddress((void**)&paob,  g_aob);
    cudaGetSymbolAddress((void**)&pgel,  g_gel);
    cudaGetSymbolAddress((void**)&pwt,   g_wt);

    cudaFuncSetAttribute(mma_gemm_k<0,1>, cudaFuncAttributeMaxDynamicSharedMemorySize, GEMM_SMEM);
    cudaFuncSetAttribute(mma_gemm_k<2,0>, cudaFuncAttributeMaxDynamicSharedMemorySize, GEMM_SMEM);
    cudaFuncSetAttribute(mma_gemm_k<1,1>, cudaFuncAttributeMaxDynamicSharedMemorySize, GEMM_SMEM);

    zero_k<<<(MTOK + 255) / 256, 256>>>();
    scat_k<<<(BATCH * NMASK + 255) / 256, 256>>>(midx);
    build_x_k<<<dim3(NTOK, BATCH), 128>>>(img, pos_table, val_table, patch_W,
                                          patch_b, mask_token, vlen);

    for (int l = 0; l < LAYERS; l++) {
        __nv_bfloat16* wl = pwt + (size_t)l * WT_LSTRIDE;
        tr_k<<<dim3(1536 / 32, 512 / 32),  256>>>(Wqkv + (size_t)l * 512 * 1536, wl + WT_QKV, 512, 1536);
        tr_k<<<dim3(512 / 32,  512 / 32),  256>>>(Wo   + (size_t)l * 512 * 512,  wl + WT_O,   512, 512);
        tr_k<<<dim3(2048 / 32, 512 / 32),  256>>>(W1   + (size_t)l * 512 * 2048, wl + WT_W1,  512, 2048);
        tr_k<<<dim3(512 / 32,  2048 / 32), 256>>>(W2   + (size_t)l * 2048 * 512, wl + WT_W2, 2048, 512);
    }

    const int gy = (MTOK + BM - 1) / BM;  // 113
    for (int l = 0; l < LAYERS; l++) {
        __nv_bfloat16* wl = pwt + (size_t)l * WT_LSTRIDE;
        ln_k<<<MTOK, 256>>>(px, ln1_s + l * DIM, ln1_b + l * DIM, phb);
        mma_gemm_k<0,1><<<dim3(12, gy), 256, GEMM_SMEM>>>(
            phb, wl + WT_QKV, bqkv + (size_t)l * 3 * DIM, nullptr, pqkvb, MTOK, 3 * DIM, DIM);
        fattn_k<<<dim3((NTOK + BQ - 1) / BQ, NHEAD, BATCH), 128>>>(pqkvb, paob);
        mma_gemm_k<2,0><<<dim3(4, gy), 256, GEMM_SMEM>>>(
            paob, wl + WT_O, bo + (size_t)l * DIM, px, px, MTOK, DIM, DIM);
        ln_k<<<MTOK, 256>>>(px, ln2_s + l * DIM, ln2_b + l * DIM, phb);
        mma_gemm_k<1,1><<<dim3(16, gy), 256, GEMM_SMEM>>>(
            phb, wl + WT_W1, b1 + (size_t)l * MLPD, nullptr, pgel, MTOK, MLPD, DIM);
        mma_gemm_k<2,0><<<dim3(4, gy), 256, GEMM_SMEM>>>(
            pgel, wl + WT_W2, b2 + (size_t)l * DIM, px, px, MTOK, DIM, MLPD);
    }

    loss_k<<<BATCH * NMASK, 192>>>(px, midx, Wt, bt, img);
    fin_k<<<1, 1>>>((float*)d_out);
}

// round 5
// speedup vs baseline: 8.1405x; 1.0872x over previous
#include <cuda_runtime.h>
#include <cuda_bf16.h>
#include <math.h>
#include <cstdint>

// ---------------- problem constants ----------------
#define BATCH   8
#define NC      3
#define HH      24
#define WW      150
#define PP      2
#define WSEG    75
#define NTOK    1800
#define PD      6
#define DIM     512
#define LAYERS  4
#define NHEAD   8
#define DHEAD   64
#define MLPD    2048
#define NMASK   900
#define MTOK    (BATCH*NTOK) // 14400
#define SCALE   0.125f

// ---------------- scratch (device globals; allocation-free) ----------------
__device__ __align__(128) float          g_x   [(size_t)MTOK * DIM];
__device__ __align__(128) __nv_bfloat16  g_qkvb[(size_t)MTOK * 3 * DIM];
__device__ __align__(128) __nv_bfloat16  g_hb  [(size_t)MTOK * DIM];
__device__ __align__(128) __nv_bfloat16  g_aob [(size_t)MTOK * DIM];
__device__ __align__(128) __nv_bfloat16  g_gel [(size_t)MTOK * MLPD];
__device__ __align__(128) __nv_bfloat16  g_wt  [(size_t)12582912];   // transposed bf16 weights
__device__ int    g_mask[MTOK];
__device__ double g_sum;

// weight-transpose layout (per layer block of 3145728 bf16)
#define WT_LSTRIDE 3145728
#define WT_QKV     0
#define WT_O       786432
#define WT_W1      1048576
#define WT_W2      2097152

// ---------------- helpers ----------------
__device__ __forceinline__ uint32_t smem_to_u32(const void* p) {
    uint32_t a;
    asm("{ .reg .u64 t; cvta.to.shared.u64 t, %1; cvt.u32.u64 %0, t; }" : "=r"(a) : "l"(p));
    return a;
}
__device__ __forceinline__ void ldsm_x4(uint32_t* r, uint32_t addr) {
    asm volatile("ldmatrix.sync.aligned.m8n8.x4.shared.b16 {%0,%1,%2,%3}, [%4];"
        : "=r"(r[0]), "=r"(r[1]), "=r"(r[2]), "=r"(r[3]) : "r"(addr));
}
__device__ __forceinline__ void ldsm_x4_t(uint32_t* r, uint32_t addr) {
    asm volatile("ldmatrix.sync.aligned.m8n8.x4.trans.shared.b16 {%0,%1,%2,%3}, [%4];"
        : "=r"(r[0]), "=r"(r[1]), "=r"(r[2]), "=r"(r[3]) : "r"(addr));
}
__device__ __forceinline__ void mma16816(float* d, const uint32_t* a, const uint32_t* b) {
    asm volatile(
        "mma.sync.aligned.m16n8k16.row.col.f32.bf16.bf16.f32 "
        "{%0,%1,%2,%3}, {%4,%5,%6,%7}, {%8,%9}, {%0,%1,%2,%3};"
        : "+f"(d[0]), "+f"(d[1]), "+f"(d[2]), "+f"(d[3])
        : "r"(a[0]), "r"(a[1]), "r"(a[2]), "r"(a[3]), "r"(b[0]), "r"(b[1]));
}
__device__ __forceinline__ void cp16(uint32_t dst, const void* src, uint32_t sz) {
    asm volatile("cp.async.ca.shared.global [%0], [%1], 16, %2;"
        :: "r"(dst), "l"(src), "r"(sz) : "memory");
}
#define CP_COMMIT() asm volatile("cp.async.commit_group;" ::: "memory")
#define CP_WAIT0()  asm volatile("cp.async.wait_group 0;"  ::: "memory")
#define CP_WAIT1()  asm volatile("cp.async.wait_group 1;"  ::: "memory")

__device__ __forceinline__ uint32_t packbf(float a, float b) {
    __nv_bfloat162 t = __floats2bfloat162_rn(a, b);
    return *(uint32_t*)&t;
}
__device__ __forceinline__ float gelu_tanh(float x) {
    const float c = 0.7978845608028654f;
    float t = tanhf(c * (x + 0.044715f * x * x * x));
    return 0.5f * x * (1.0f + t);
}

// ---------------- setup kernels ----------------
__global__ void zero_k() {
    int i = blockIdx.x * 256 + threadIdx.x;
    if (i < MTOK) g_mask[i] = 0;
    if (i == 0)   g_sum = 0.0;
}
__global__ void scat_k(const int* __restrict__ midx) {
    int i = blockIdx.x * 256 + threadIdx.x;
    if (i < BATCH * NMASK) g_mask[(i / NMASK) * NTOK + midx[i]] = 1;
}

__global__ __launch_bounds__(128) void build_x_k(
    const float* __restrict__ img, const float* __restrict__ pos_table,
    const float* __restrict__ val_table, const float* __restrict__ patch_W,
    const float* __restrict__ patch_b, const float* __restrict__ mask_token,
    const int* __restrict__ valid_length)
{
    int n = blockIdx.x, b = blockIdx.y, t = threadIdx.x;
    __shared__ float pv[PD];
    __shared__ int sm_mask, sm_seg;
    int hh = n / WSEG, ws = n % WSEG;
    if (t < PD) {
        int p = t / NC, c = t % NC;
        pv[t] = img[(((size_t)b * NC + c) * HH + hh) * WW + ws * PP + p];
    } else if (t == 8) {
        sm_mask = g_mask[b * NTOK + n];
    } else if (t == 9) {
        int vl = valid_length[b];
        if (vl == 150) vl = 149;
        int nv = (vl + 1) >> 1;
        sm_seg = (ws < nv) ? 1 : 0;
    }
    __syncthreads();
    float p0 = pv[0], p1 = pv[1], p2 = pv[2], p3 = pv[3], p4 = pv[4], p5 = pv[5];
    int msk = sm_mask, seg = sm_seg;
    size_t rowo = ((size_t)(b * NTOK + n)) * DIM;
    for (int d = t; d < DIM; d += 128) {
        float pos = pos_table[(size_t)(n + 1) * DIM + d] + val_table[(size_t)seg * DIM + d];
        float v;
        if (msk) v = mask_token[d] + pos;
        else {
            v = patch_b[d]
              + p0 * patch_W[0 * DIM + d] + p1 * patch_W[1 * DIM + d]
              + p2 * patch_W[2 * DIM + d] + p3 * patch_W[3 * DIM + d]
              + p4 * patch_W[4 * DIM + d] + p5 * patch_W[5 * DIM + d];
            v += pos;
        }
        g_x[rowo + d] = v;
    }
}

// ---------------- weight transpose: W[K,N] fp32 -> WT[N,K] bf16 ----------------
__global__ __launch_bounds__(256) void tr_k(const float* __restrict__ W,
                                            __nv_bfloat16* __restrict__ WT, int K, int N)
{
    __shared__ float t[32][33];
    int n0 = blockIdx.x * 32, k0 = blockIdx.y * 32;
    int tx = threadIdx.x & 31, ty = threadIdx.x >> 5;
    #pragma unroll
    for (int i = 0; i < 4; i++) {
        int k = ty * 4 + i;
        t[k][tx] = W[(size_t)(k0 + k) * N + n0 + tx];
    }
    __syncthreads();
    #pragma unroll
    for (int i = 0; i < 4; i++) {
        int n = ty * 4 + i;
        WT[(size_t)(n0 + n) * K + k0 + tx] = __float2bfloat16(t[tx][n]);
    }
}

// ---------------- layernorm (fp32 in -> bf16 out) ----------------
__global__ __launch_bounds__(256) void ln_k(
    const float* __restrict__ x, const float* __restrict__ gam,
    const float* __restrict__ bet, __nv_bfloat16* __restrict__ out)
{
    int r = blockIdx.x, t = threadIdx.x;
    const float* xr = x + (size_t)r * DIM;
    float v0 = xr[t], v1 = xr[t + 256];
    float sum = v0 + v1, sq = v0 * v0 + v1 * v1;
    __shared__ float sh[64];
    #pragma unroll
    for (int o = 16; o > 0; o >>= 1) {
        sum += __shfl_xor_sync(0xffffffffu, sum, o);
        sq  += __shfl_xor_sync(0xffffffffu, sq,  o);
    }
    int warp = t >> 5, lane = t & 31;
    if (lane == 0) { sh[warp] = sum; sh[warp + 32] = sq; }
    __syncthreads();
    if (t == 0) {
        float ts = 0.f, tq = 0.f;
        #pragma unroll
        for (int i = 0; i < 8; i++) { ts += sh[i]; tq += sh[32 + i]; }
        float mean = ts * (1.0f / DIM);
        float var  = tq * (1.0f / DIM) - mean * mean;
        sh[0] = mean; sh[1] = rsqrtf(var + 1e-5f);
    }
    __syncthreads();
    float mean = sh[0], rstd = sh[1];
    out[(size_t)r * DIM + t]       = __float2bfloat16((v0 - mean) * rstd * gam[t]       + bet[t]);
    out[(size_t)r * DIM + t + 256] = __float2bfloat16((v1 - mean) * rstd * gam[t + 256] + bet[t + 256]);
}

// ---------------- HMMA bf16 GEMM, 128x128x32 tiles, 3-stage cp.async ----------------
#define BM 128
#define BN 128
#define BK 32
#define LDP 40   // padded row stride (80B): 16B-aligned rows, conflict-free ldmatrix
#define GEMM_SMEM (6 * BM * LDP * 2)   // 61440

template <int EPI, int OUTB>
__global__ __launch_bounds__(256) void mma_gemm_k(
    const __nv_bfloat16* __restrict__ A, const __nv_bfloat16* __restrict__ B,
    const float* __restrict__ bias, const float* __restrict__ R,
    void* __restrict__ Cout, int M, int N, int K)
{
    extern __shared__ __align__(16) __nv_bfloat16 sm_g[];
    __nv_bfloat16* As = sm_g;
    __nv_bfloat16* Bs = sm_g + 3 * BM * LDP;

    const int tid = threadIdx.x, lane = tid & 31, wid = tid >> 5;
    const int wm = wid >> 2, wn = wid & 3;
    const int m0 = blockIdx.y * BM, n0 = blockIdx.x * BN;

    const uint32_t sAu = smem_to_u32(As);
    const uint32_t sBu = smem_to_u32(Bs);
    const uint32_t ABYT = BM * LDP * 2;

    float acc[4][4][4];
    #pragma unroll
    for (int i = 0; i < 4; i++)
        #pragma unroll
        for (int j = 0; j < 4; j++)
            #pragma unroll
            for (int q = 0; q < 4; q++) acc[i][j][q] = 0.f;

    const int NK = K >> 5;
    auto issue = [&](int kt, int st) {
        #pragma unroll
        for (int i = 0; i < 2; i++) {
            int ch = tid + i * 256;
            int row = ch >> 2, c8 = (ch & 3) * 8;
            uint32_t da = sAu + st * ABYT + (uint32_t)(row * LDP + c8) * 2;
            cp16(da, A + (size_t)(m0 + row) * K + kt * BK + c8, (m0 + row) < M ? 16u : 0u);
            uint32_t db = sBu + st * ABYT + (uint32_t)(row * LDP + c8) * 2;
            cp16(db, B + (size_t)(n0 + row) * K + kt * BK + c8, 16u);
        }
        CP_COMMIT();
    };
    issue(0, 0);
    issue(1, 1);

    const int a_r = wm * 64 + (lane & 15);
    const int a_c = (lane >> 4) * 8;
    const int b_r = wn * 32 + (lane & 7) + ((lane >> 4) << 3);
    const int b_c = ((lane >> 3) & 1) * 8;

    int st = 0;
    for (int kt = 0; kt < NK; kt++) {
        CP_WAIT1();
        __syncthreads();
        if (kt + 2 < NK) issue(kt + 2, (kt + 2) % 3);
        else CP_COMMIT();
        const uint32_t sa = sAu + st * ABYT;
        const uint32_t sb = sBu + st * ABYT;
        #pragma unroll
        for (int ks = 0; ks < 2; ks++) {
            uint32_t af[4][4], bf2[2][4];
            #pragma unroll
            for (int mi = 0; mi < 4; mi++)
                ldsm_x4(af[mi], sa + (uint32_t)(((a_r + mi * 16) * LDP) + ks * 16 + a_c) * 2u);
            #pragma unroll
            for (int nj = 0; nj < 2; nj++)
                ldsm_x4(bf2[nj], sb + (uint32_t)(((b_r + nj * 16) * LDP) + ks * 16 + b_c) * 2u);
            #pragma unroll
            for (int mi = 0; mi < 4; mi++)
                #pragma unroll
                for (int nj = 0; nj < 4; nj++)
                    mma16816(acc[mi][nj], af[mi], &bf2[nj >> 1][(nj & 1) * 2]);
        }
        st++; if (st == 3) st = 0;
    }

    // epilogue
    const int r_lane = (lane >> 2);
    const int c_lane = (lane & 3) * 2;
    #pragma unroll
    for (int mi = 0; mi < 4; mi++) {
        const int r0 = m0 + wm * 64 + mi * 16 + r_lane;
        #pragma unroll
        for (int half = 0; half < 2; half++) {
            const int row = r0 + half * 8;
            if (row >= M) continue;
            #pragma unroll
            for (int nj = 0; nj < 4; nj++) {
                const int c = n0 + wn * 32 + nj * 8 + c_lane;
                float v0 = acc[mi][nj][half * 2 + 0] + bias[c];
                float v1 = acc[mi][nj][half * 2 + 1] + bias[c + 1];
                if (EPI == 1) { v0 = gelu_tanh(v0); v1 = gelu_tanh(v1); }
                if (EPI == 2) {
                    float2 rr = *(const float2*)(R + (size_t)row * N + c);
                    v0 += rr.x; v1 += rr.y;
                }
                if (OUTB) {
                    *(__nv_bfloat162*)((__nv_bfloat16*)Cout + (size_t)row * N + c) =
                        __floats2bfloat162_rn(v0, v1);
                } else {
                    *(float2*)((float*)Cout + (size_t)row * N + c) = make_float2(v0, v1);
                }
            }
        }
    }
}

// ---------------- HMMA bf16 flash attention ----------------
// 128 queries/CTA (8 warps x m16), 64-key tiles, K and V via cp.async,
// V consumed with ldmatrix.trans (no in-kernel transpose).
#define BQ  128
#define BKV 64
#define KVP 72
#define NKT ((NTOK + BKV - 1) / BKV)   // 29

__global__ __launch_bounds__(256) void fattn_k(const __nv_bfloat16* __restrict__ qkv,
                                               __nv_bfloat16* __restrict__ out)
{
    const int b = blockIdx.z, h = blockIdx.y;
    const int q0 = blockIdx.x * BQ;
    const int tid = threadIdx.x, lane = tid & 31, wid = tid >> 5;
    const int qw = q0 + wid * 16;

    __shared__ __align__(16) __nv_bfloat16 KsS[2][BKV * KVP];
    __shared__ __align__(16) __nv_bfloat16 VsS[2][BKV * KVP];   // row-major [kv][dim]

    const size_t tokb = (size_t)b * NTOK;
    const size_t rstr = 3 * DIM;
    const int hb = h * DHEAD;
    const uint32_t ksu = smem_to_u32(KsS);
    const uint32_t vsu = smem_to_u32(VsS);
    const uint32_t KVBYT = BKV * KVP * 2;

    // Q fragments (scaled by 0.125 -- exact in bf16)
    uint32_t qa[4][4];
    {
        int r = lane >> 2, c = (lane & 3) * 2;
        #pragma unroll
        for (int ks = 0; ks < 4; ks++)
            #pragma unroll
            for (int p = 0; p < 4; p++) {
                int rr = qw + r + (p & 1) * 8;
                if (rr > NTOK - 1) rr = NTOK - 1;
                int cc = ks * 16 + (p >> 1) * 8 + c;
                __nv_bfloat162 v = *(const __nv_bfloat162*)(qkv + (tokb + rr) * rstr + hb + cc);
                float2 f = __bfloat1622float2(v);
                qa[ks][p] = packbf(f.x * SCALE, f.y * SCALE);
            }
    }

    float o[8][4];
    #pragma unroll
    for (int j = 0; j < 8; j++)
        #pragma unroll
        for (int q = 0; q < 4; q++) o[j][q] = 0.f;
    float m0v = -1e30f, m1v = -1e30f, l0 = 0.f, l1 = 0.f;

    auto stageKV = [&](int kt, int bufi) {
        #pragma unroll
        for (int i = 0; i < 2; i++) {
            int ch = tid + i * 256;              // 0..511
            int row = ch >> 3, c8 = (ch & 7) * 8;
            int kr = kt * BKV + row;
            int krc = kr < NTOK ? kr : 0;
            uint32_t sz = kr < NTOK ? 16u : 0u;
            uint32_t so = (uint32_t)(row * KVP + c8) * 2;
            const __nv_bfloat16* base = qkv + (tokb + krc) * rstr + hb + c8;
            cp16(ksu + bufi * KVBYT + so, base + DIM,     sz);
            cp16(vsu + bufi * KVBYT + so, base + 2 * DIM, sz);
        }
        CP_COMMIT();
    };

    stageKV(0, 0);

    const int lr   = (lane & 7) + ((lane >> 4) << 3);
    const int lc   = ((lane >> 3) & 1) * 8;
    const int tr_r = lane & 15;
    const int tr_c = (lane >> 4) * 8;

    for (int kt = 0; kt < NKT; kt++) {
        const int bufi = kt & 1;
        if (kt + 1 < NKT) { stageKV(kt + 1, bufi ^ 1); CP_WAIT1(); }
        else              { CP_WAIT0(); }
        __syncthreads();

        // S = Q @ K^T (16 x 64 per warp)
        float s[8][4];
        #pragma unroll
        for (int j = 0; j < 8; j++)
            #pragma unroll
            for (int q = 0; q < 4; q++) s[j][q] = 0.f;
        const uint32_t kb = ksu + bufi * KVBYT;
        #pragma unroll
        for (int nj = 0; nj < 4; nj++)
            #pragma unroll
            for (int ks = 0; ks < 4; ks++) {
                uint32_t bf[4];
                ldsm_x4(bf, kb + (uint32_t)((nj * 16 + lr) * KVP + ks * 16 + lc) * 2u);
                mma16816(s[nj * 2],     qa[ks], bf);
                mma16816(s[nj * 2 + 1], qa[ks], bf + 2);
            }

        if (kt == NKT - 1) {
            #pragma unroll
            for (int j = 0; j < 8; j++) {
                int gc = kt * BKV + j * 8 + (lane & 3) * 2;
                if (gc     >= NTOK) { s[j][0] = -1e30f; s[j][2] = -1e30f; }
                if (gc + 1 >= NTOK) { s[j][1] = -1e30f; s[j][3] = -1e30f; }
            }
        }

        // online softmax
        float mt0 = -1e30f, mt1 = -1e30f;
        #pragma unroll
        for (int j = 0; j < 8; j++) {
            mt0 = fmaxf(mt0, fmaxf(s[j][0], s[j][1]));
            mt1 = fmaxf(mt1, fmaxf(s[j][2], s[j][3]));
        }
        mt0 = fmaxf(mt0, __shfl_xor_sync(0xffffffffu, mt0, 1));
        mt0 = fmaxf(mt0, __shfl_xor_sync(0xffffffffu, mt0, 2));
        mt1 = fmaxf(mt1, __shfl_xor_sync(0xffffffffu, mt1, 1));
        mt1 = fmaxf(mt1, __shfl_xor_sync(0xffffffffu, mt1, 2));
        float mn0 = fmaxf(m0v, mt0), mn1 = fmaxf(m1v, mt1);
        float c0 = __expf(m0v - mn0), c1 = __expf(m1v - mn1);
        l0 *= c0; l1 *= c1;
        #pragma unroll
        for (int j = 0; j < 8; j++) {
            float p0 = __expf(s[j][0] - mn0), p1 = __expf(s[j][1] - mn0);
            float p2 = __expf(s[j][2] - mn1), p3 = __expf(s[j][3] - mn1);
            l0 += p0 + p1; l1 += p2 + p3;
            s[j][0] = p0; s[j][1] = p1; s[j][2] = p2; s[j][3] = p3;
        }
        uint32_t pa[4][4];
        #pragma unroll
        for (int ks = 0; ks < 4; ks++) {
            pa[ks][0] = packbf(s[2 * ks][0],     s[2 * ks][1]);
            pa[ks][1] = packbf(s[2 * ks][2],     s[2 * ks][3]);
            pa[ks][2] = packbf(s[2 * ks + 1][0], s[2 * ks + 1][1]);
            pa[ks][3] = packbf(s[2 * ks + 1][2], s[2 * ks + 1][3]);
        }
        #pragma unroll
        for (int jj = 0; jj < 8; jj++) {
            o[jj][0] *= c0; o[jj][1] *= c0; o[jj][2] *= c1; o[jj][3] *= c1;
        }
        m0v = mn0; m1v = mn1;

        // O += P @ V   (V row-major [kv][dim], B-fragments via ldmatrix.trans)
        const uint32_t vb = vsu + bufi * KVBYT;
        #pragma unroll
        for (int nj = 0; nj < 4; nj++)
            #pragma unroll
            for (int ks = 0; ks < 4; ks++) {
                uint32_t bf[4];
                ldsm_x4_t(bf, vb + (uint32_t)((ks * 16 + tr_r) * KVP + nj * 16 + tr_c) * 2u);
                mma16816(o[nj * 2],     pa[ks], bf);
                mma16816(o[nj * 2 + 1], pa[ks], bf + 2);
            }

        __syncthreads();
    }

    l0 += __shfl_xor_sync(0xffffffffu, l0, 1);
    l0 += __shfl_xor_sync(0xffffffffu, l0, 2);
    l1 += __shfl_xor_sync(0xffffffffu, l1, 1);
    l1 += __shfl_xor_sync(0xffffffffu, l1, 2);
    float i0 = 1.f / l0, i1 = 1.f / l1;
    int r0 = qw + (lane >> 2), r1 = r0 + 8;
    int cb = hb + (lane & 3) * 2;
    if (r0 < NTOK) {
        __nv_bfloat16* op = out + (tokb + r0) * DIM;
        #pragma unroll
        for (int jj = 0; jj < 8; jj++)
            *(__nv_bfloat162*)(op + cb + jj * 8) = __floats2bfloat162_rn(o[jj][0] * i0, o[jj][1] * i0);
    }
    if (r1 < NTOK) {
        __nv_bfloat16* op = out + (tokb + r1) * DIM;
        #pragma unroll
        for (int jj = 0; jj < 8; jj++)
            *(__nv_bfloat162*)(op + cb + jj * 8) = __floats2bfloat162_rn(o[jj][2] * i1, o[jj][3] * i1);
    }
}

// ---------------- masked-patch prediction + L1 loss ----------------
__global__ __launch_bounds__(192) void loss_k(
    const float* __restrict__ xenc, const int* __restrict__ midx,
    const float* __restrict__ Wt, const float* __restrict__ bt,
    const float* __restrict__ img)
{
    int bm = blockIdx.x;
    int b  = bm / NMASK, mm = bm % NMASK;
    int n  = midx[b * NMASK + mm];
    const float* e = xenc + ((size_t)(b * NTOK + n)) * DIM;
    int w = threadIdx.x >> 5, lane = threadIdx.x & 31;

    float acc = 0.f;
    for (int k = lane; k < DIM; k += 32) acc += e[k] * Wt[(size_t)k * PD + w];
    #pragma unroll
    for (int o = 16; o > 0; o >>= 1) acc += __shfl_xor_sync(0xffffffffu, acc, o);

    if (lane == 0) {
        float pred = acc + bt[w];
        int hh = n / WSEG, ws = n % WSEG;
        int p = w / NC, c = w % NC;
        float patch = img[(((size_t)b * NC + c) * HH + hh) * WW + ws * PP + p];
        atomicAdd(&g_sum, (double)fabsf(pred - patch));
    }
}

__global__ void fin_k(float* __restrict__ out) {
    out[0] = (float)(g_sum / (43200.0 * 900.0));
}

// ---------------- launch ----------------
extern "C" void kernel_launch(void* const* d_in, const int* in_sizes, int n_in,
                              void* d_out, int out_size)
{
    const float* img        = (const float*)d_in[0];
    const float* pos_table  = (const float*)d_in[1];
    const float* val_table  = (const float*)d_in[2];
    const float* patch_W    = (const float*)d_in[3];
    const float* patch_b    = (const float*)d_in[4];
    const float* mask_token = (const float*)d_in[5];
    const float* ln1_s      = (const float*)d_in[6];
    const float* ln1_b      = (const float*)d_in[7];
    const float* Wqkv       = (const float*)d_in[8];
    const float* bqkv       = (const float*)d_in[9];
    const float* Wo         = (const float*)d_in[10];
    const float* bo         = (const float*)d_in[11];
    const float* ln2_s      = (const float*)d_in[12];
    const float* ln2_b      = (const float*)d_in[13];
    const float* W1         = (const float*)d_in[14];
    const float* b1         = (const float*)d_in[15];
    const float* W2         = (const float*)d_in[16];
    const float* b2         = (const float*)d_in[17];
    const float* Wt         = (const float*)d_in[18];
    const float* bt         = (const float*)d_in[19];
    const int*   vlen       = (const int*)d_in[20];
    const int*   midx       = (const int*)d_in[21];

    float* px;
    __nv_bfloat16 *pqkvb, *phb, *paob, *pgel, *pwt;
    cudaGetSymbolAddress((void**)&px,    g_x);
    cudaGetSymbolAddress((void**)&pqkvb, g_qkvb);
    cudaGetSymbolAddress((void**)&phb,   g_hb);
    cudaGetSymbolAddress((void**)&paob,  g_aob);
    cudaGetSymbolAddress((void**)&pgel,  g_gel);
    cudaGetSymbolAddress((void**)&pwt,   g_wt);

    cudaFuncSetAttribute(mma_gemm_k<0,1>, cudaFuncAttributeMaxDynamicSharedMemorySize, GEMM_SMEM);
    cudaFuncSetAttribute(mma_gemm_k<2,0>, cudaFuncAttributeMaxDynamicSharedMemorySize, GEMM_SMEM);
    cudaFuncSetAttribute(mma_gemm_k<1,1>, cudaFuncAttributeMaxDynamicSharedMemorySize, GEMM_SMEM);

    const int gy = (MTOK + BM - 1) / BM;  // 113

    // launches 1-5: setup; launch 6 = QKV GEMM layer 0 (ncu -s 5 -c 1 profiles it)
    zero_k<<<(MTOK + 255) / 256, 256>>>();
    scat_k<<<(BATCH * NMASK + 255) / 256, 256>>>(midx);
    build_x_k<<<dim3(NTOK, BATCH), 128>>>(img, pos_table, val_table, patch_W,
                                          patch_b, mask_token, vlen);
    tr_k<<<dim3(1536 / 32, 512 / 32), 256>>>(Wqkv, pwt + WT_QKV, 512, 1536);
    ln_k<<<MTOK, 256>>>(px, ln1_s, ln1_b, phb);
    mma_gemm_k<0,1><<<dim3(12, gy), 256, GEMM_SMEM>>>(
        phb, pwt + WT_QKV, bqkv, nullptr, pqkvb, MTOK, 3 * DIM, DIM);

    // remaining weight transposes
    tr_k<<<dim3(512 / 32,  512 / 32),  256>>>(Wo, pwt + WT_O, 512, 512);
    tr_k<<<dim3(2048 / 32, 512 / 32),  256>>>(W1, pwt + WT_W1, 512, 2048);
    tr_k<<<dim3(512 / 32,  2048 / 32), 256>>>(W2, pwt + WT_W2, 2048, 512);
    for (int l = 1; l < LAYERS; l++) {
        __nv_bfloat16* wl = pwt + (size_t)l * WT_LSTRIDE;
        tr_k<<<dim3(1536 / 32, 512 / 32),  256>>>(Wqkv + (size_t)l * 512 * 1536, wl + WT_QKV, 512, 1536);
        tr_k<<<dim3(512 / 32,  512 / 32),  256>>>(Wo   + (size_t)l * 512 * 512,  wl + WT_O,   512, 512);
        tr_k<<<dim3(2048 / 32, 512 / 32),  256>>>(W1   + (size_t)l * 512 * 2048, wl + WT_W1,  512, 2048);
        tr_k<<<dim3(512 / 32,  2048 / 32), 256>>>(W2   + (size_t)l * 2048 * 512, wl + WT_W2, 2048, 512);
    }

    for (int l = 0; l < LAYERS; l++) {
        __nv_bfloat16* wl = pwt + (size_t)l * WT_LSTRIDE;
        if (l > 0) {
            ln_k<<<MTOK, 256>>>(px, ln1_s + l * DIM, ln1_b + l * DIM, phb);
            mma_gemm_k<0,1><<<dim3(12, gy), 256, GEMM_SMEM>>>(
                phb, wl + WT_QKV, bqkv + (size_t)l * 3 * DIM, nullptr, pqkvb, MTOK, 3 * DIM, DIM);
        }
        fattn_k<<<dim3((NTOK + BQ - 1) / BQ, NHEAD, BATCH), 256>>>(pqkvb, paob);
        mma_gemm_k<2,0><<<dim3(4, gy), 256, GEMM_SMEM>>>(
            paob, wl + WT_O, bo + (size_t)l * DIM, px, px, MTOK, DIM, DIM);
        ln_k<<<MTOK, 256>>>(px, ln2_s + l * DIM, ln2_b + l * DIM, phb);
        mma_gemm_k<1,1><<<dim3(16, gy), 256, GEMM_SMEM>>>(
            phb, wl + WT_W1, b1 + (size_t)l * MLPD, nullptr, pgel, MTOK, MLPD, DIM);
        mma_gemm_k<2,0><<<dim3(4, gy), 256, GEMM_SMEM>>>(
            pgel, wl + WT_W2, b2 + (size_t)l * DIM, px, px, MTOK, DIM, MLPD);
    }

    loss_k<<<BATCH * NMASK, 192>>>(px, midx, Wt, bt, img);
    fin_k<<<1, 1>>>((float*)d_out);
}